// round 2
// baseline (speedup 1.0000x reference)
#include <cuda_runtime.h>

#define Tn 512
#define Sn 1024
#define Bn 16
#define An 512
#define Hn 8
#define Dn 64
#define ROWPITCH (Bn * An) /* 8192 floats between consecutive t or s rows */

// Scratch (allocation-free per harness rules)
__device__ float g_vh[(size_t)Sn * Bn * An];    // v-projected keys, same layout as keys
__device__ float g_vals[(size_t)Tn * Bn * An];  // attention output pre o-proj

// Load a 64x64 fp32 tile (global row pitch = gpitch floats) TRANSPOSED into
// smem tile sm[j][r] with row pitch 68 floats (16B-aligned rows). Global loads
// are fully coalesced float4; smem stores take a benign 8-way conflict.
__device__ __forceinline__ void load_tile_T(float* sm, const float* __restrict__ g,
                                            int gpitch, float scale) {
    int tid = threadIdx.x;
#pragma unroll
    for (int i = tid; i < 1024; i += 256) {
        int r = i >> 4;
        int j = (i & 15) << 2;
        float4 v = *(const float4*)(g + (size_t)r * gpitch + j);
        sm[(j + 0) * 68 + r] = v.x * scale;
        sm[(j + 1) * 68 + r] = v.y * scale;
        sm[(j + 2) * 68 + r] = v.z * scale;
        sm[(j + 3) * 68 + r] = v.w * scale;
    }
}

// ---------------------------------------------------------------------------
// Kernel 1: Vh[r][i] = sum_j K2d[r][j] * vw[i][j] + vb[i]
// K2d is keys viewed as [S*B*H, 64] (exactly contiguous in that order).
// ---------------------------------------------------------------------------
__global__ void __launch_bounds__(256) vproj_kernel(const float* __restrict__ keys,
                                                    const float* __restrict__ vw,
                                                    const float* __restrict__ vb) {
    __shared__ float a_sm[64 * 68];  // keys chunk transposed [j][r]
    __shared__ float w_sm[64 * 68];  // vw transposed        [j][i]
    const size_t rowbase = (size_t)blockIdx.x * 64;

    load_tile_T(a_sm, keys + rowbase * 64, 64, 1.0f);
    load_tile_T(w_sm, vw, 64, 1.0f);
    __syncthreads();

    const int ty = threadIdx.x >> 4, tx = threadIdx.x & 15;
    const int r0 = ty * 4, c0 = tx * 4;

    float4 bias = *(const float4*)(vb + c0);
    float acc[4][4];
#pragma unroll
    for (int rr = 0; rr < 4; rr++) {
        acc[rr][0] = bias.x; acc[rr][1] = bias.y;
        acc[rr][2] = bias.z; acc[rr][3] = bias.w;
    }

#pragma unroll 8
    for (int j = 0; j < 64; j++) {
        float4 a = *(const float4*)&a_sm[j * 68 + r0];
        float4 b = *(const float4*)&w_sm[j * 68 + c0];
        float av[4] = {a.x, a.y, a.z, a.w};
        float bv[4] = {b.x, b.y, b.z, b.w};
#pragma unroll
        for (int rr = 0; rr < 4; rr++)
#pragma unroll
            for (int cc = 0; cc < 4; cc++) acc[rr][cc] = fmaf(av[rr], bv[cc], acc[rr][cc]);
    }

#pragma unroll
    for (int rr = 0; rr < 4; rr++) {
        float4 o = make_float4(acc[rr][0], acc[rr][1], acc[rr][2], acc[rr][3]);
        *(float4*)(g_vh + (rowbase + r0 + rr) * 64 + c0) = o;
    }
}

// ---------------------------------------------------------------------------
// Kernel 2: flash attention per (b, h, t-tile of 64). 256 threads, 4x4/thread.
// Mask is read as 32-bit words (nonzero = keep) — correct for either int32 or
// float32 widening of the boolean mask.
// ---------------------------------------------------------------------------
__global__ void __launch_bounds__(256) attn_kernel(const float* __restrict__ q,
                                                   const float* __restrict__ k,
                                                   const unsigned int* __restrict__ mask) {
    extern __shared__ float sm[];
    float* q_sm  = sm;                // [j][r] pitch 68, Q pre-scaled by 1/8
    float* kp_sm = sm + 64 * 68;      // K transposed [j][c]; reused as P [s][r]
    float* v_sm  = sm + 2 * 64 * 68;  // [s][d] pitch 64

    const int tid = threadIdx.x;
    const int t0 = blockIdx.x * 64;
    const int h = blockIdx.y;
    const int b = blockIdx.z;
    const int ty = tid >> 4, tx = tid & 15;
    const int r0 = ty * 4, c0 = tx * 4;

    load_tile_T(q_sm, q + ((size_t)t0 * Bn + b) * An + h * 64, ROWPITCH, 0.125f);

    float oacc[4][4];
#pragma unroll
    for (int rr = 0; rr < 4; rr++)
#pragma unroll
        for (int cc = 0; cc < 4; cc++) oacc[rr][cc] = 0.0f;
    float mrun[4] = {-1e30f, -1e30f, -1e30f, -1e30f};
    float lrun[4] = {0.f, 0.f, 0.f, 0.f};

    const unsigned int* mbase = mask + ((size_t)b * Tn + t0 + r0) * Sn;

    for (int st = 0; st < Sn / 64; st++) {
        const int s0 = st * 64;
        __syncthreads();  // previous iter readers of kp_sm/v_sm done (also covers q_sm load)

        load_tile_T(kp_sm, k + ((size_t)s0 * Bn + b) * An + h * 64, ROWPITCH, 1.0f);
        {
            const float* vsrc = g_vh + ((size_t)s0 * Bn + b) * An + h * 64;
#pragma unroll
            for (int i = tid; i < 1024; i += 256) {
                int r = i >> 4;
                int j = (i & 15) << 2;
                *(float4*)&v_sm[r * 64 + j] = *(const float4*)(vsrc + (size_t)r * ROWPITCH + j);
            }
        }
        __syncthreads();

        // ---- scores: S[r][c] = qhat[r] . k[c] ----
        float sacc[4][4];
#pragma unroll
        for (int rr = 0; rr < 4; rr++)
#pragma unroll
            for (int cc = 0; cc < 4; cc++) sacc[rr][cc] = 0.0f;
#pragma unroll 8
        for (int j = 0; j < 64; j++) {
            float4 a = *(const float4*)&q_sm[j * 68 + r0];
            float4 bq = *(const float4*)&kp_sm[j * 68 + c0];
            float av[4] = {a.x, a.y, a.z, a.w};
            float bv[4] = {bq.x, bq.y, bq.z, bq.w};
#pragma unroll
            for (int rr = 0; rr < 4; rr++)
#pragma unroll
                for (int cc = 0; cc < 4; cc++) sacc[rr][cc] = fmaf(av[rr], bv[cc], sacc[rr][cc]);
        }

        // ---- mask (32-bit words; nonzero = keep) ----
#pragma unroll
        for (int rr = 0; rr < 4; rr++) {
            uint4 mk = *(const uint4*)(mbase + (size_t)rr * Sn + s0 + c0);
            if (!mk.x) sacc[rr][0] = -1e30f;
            if (!mk.y) sacc[rr][1] = -1e30f;
            if (!mk.z) sacc[rr][2] = -1e30f;
            if (!mk.w) sacc[rr][3] = -1e30f;
        }

        // ---- online softmax (row groups = 16 lanes) ----
#pragma unroll
        for (int rr = 0; rr < 4; rr++) {
            float ml = fmaxf(fmaxf(sacc[rr][0], sacc[rr][1]), fmaxf(sacc[rr][2], sacc[rr][3]));
#pragma unroll
            for (int off = 8; off; off >>= 1) ml = fmaxf(ml, __shfl_xor_sync(0xffffffffu, ml, off));
            float mnew = fmaxf(mrun[rr], ml);
            float alpha = __expf(mrun[rr] - mnew);
            mrun[rr] = mnew;
            float ls = 0.0f;
#pragma unroll
            for (int cc = 0; cc < 4; cc++) {
                float p = __expf(sacc[rr][cc] - mnew);
                sacc[rr][cc] = p;
                ls += p;
            }
#pragma unroll
            for (int off = 8; off; off >>= 1) ls += __shfl_xor_sync(0xffffffffu, ls, off);
            lrun[rr] = lrun[rr] * alpha + ls;
#pragma unroll
            for (int cc = 0; cc < 4; cc++) oacc[rr][cc] *= alpha;
        }

        __syncthreads();  // everyone done reading kp_sm as K
        // write P transposed: kp_sm[s][r]
#pragma unroll
        for (int cc = 0; cc < 4; cc++) {
            float4 pv = make_float4(sacc[0][cc], sacc[1][cc], sacc[2][cc], sacc[3][cc]);
            *(float4*)&kp_sm[(c0 + cc) * 68 + r0] = pv;
        }
        __syncthreads();

        // ---- O += P @ V ----
#pragma unroll 8
        for (int s = 0; s < 64; s++) {
            float4 p4 = *(const float4*)&kp_sm[s * 68 + r0];
            float4 v4 = *(const float4*)&v_sm[s * 64 + c0];
            float pv[4] = {p4.x, p4.y, p4.z, p4.w};
            float vv[4] = {v4.x, v4.y, v4.z, v4.w};
#pragma unroll
            for (int rr = 0; rr < 4; rr++)
#pragma unroll
                for (int cc = 0; cc < 4; cc++) oacc[rr][cc] = fmaf(pv[rr], vv[cc], oacc[rr][cc]);
        }
    }

    // epilogue: normalize and store
    float* obase = g_vals + ((size_t)(t0 + r0) * Bn + b) * An + h * 64 + c0;
#pragma unroll
    for (int rr = 0; rr < 4; rr++) {
        float inv = 1.0f / lrun[rr];
        float4 o = make_float4(oacc[rr][0] * inv, oacc[rr][1] * inv,
                               oacc[rr][2] * inv, oacc[rr][3] * inv);
        *(float4*)(obase + (size_t)rr * ROWPITCH) = o;
    }
}

// ---------------------------------------------------------------------------
// Kernel 3: out[r][i] = sum_j vals[r][j] * ow[i][j] + ob[i]; r over T*B rows.
// ---------------------------------------------------------------------------
__global__ void __launch_bounds__(256) oproj_kernel(const float* __restrict__ ow,
                                                    const float* __restrict__ ob,
                                                    float* __restrict__ out) {
    __shared__ float a_sm[64 * 68];  // vals chunk transposed [j][r]
    __shared__ float b_sm[64 * 68];  // ow chunk transposed   [j][i]

    const int ty = threadIdx.x >> 4, tx = threadIdx.x & 15;
    const int r0 = ty * 4, c0 = tx * 4;
    const size_t rowbase = (size_t)blockIdx.x * 64;
    const int i0 = blockIdx.y * 64;

    float4 bias = *(const float4*)(ob + i0 + c0);
    float acc[4][4];
#pragma unroll
    for (int rr = 0; rr < 4; rr++) {
        acc[rr][0] = bias.x; acc[rr][1] = bias.y;
        acc[rr][2] = bias.z; acc[rr][3] = bias.w;
    }

    for (int kc = 0; kc < 8; kc++) {
        const int j0 = kc * 64;
        __syncthreads();
        load_tile_T(a_sm, g_vals + rowbase * An + j0, An, 1.0f);
        load_tile_T(b_sm, ow + (size_t)i0 * An + j0, An, 1.0f);
        __syncthreads();
#pragma unroll 8
        for (int j = 0; j < 64; j++) {
            float4 a = *(const float4*)&a_sm[j * 68 + r0];
            float4 b = *(const float4*)&b_sm[j * 68 + c0];
            float av[4] = {a.x, a.y, a.z, a.w};
            float bv[4] = {b.x, b.y, b.z, b.w};
#pragma unroll
            for (int rr = 0; rr < 4; rr++)
#pragma unroll
                for (int cc = 0; cc < 4; cc++) acc[rr][cc] = fmaf(av[rr], bv[cc], acc[rr][cc]);
        }
    }

#pragma unroll
    for (int rr = 0; rr < 4; rr++) {
        float4 o = make_float4(acc[rr][0], acc[rr][1], acc[rr][2], acc[rr][3]);
        *(float4*)(out + (rowbase + r0 + rr) * An + i0 + c0) = o;
    }
}

// ---------------------------------------------------------------------------
extern "C" void kernel_launch(void* const* d_in, const int* in_sizes, int n_in,
                              void* d_out, int out_size) {
    const float* q = (const float*)d_in[0];
    const float* k = (const float*)d_in[1];
    const unsigned int* mask = (const unsigned int*)d_in[2];
    const float* vw = (const float*)d_in[3];
    const float* vb = (const float*)d_in[4];
    const float* ow = (const float*)d_in[5];
    const float* ob = (const float*)d_in[6];
    float* out = (float*)d_out;

    // 1) v-projection of keys
    vproj_kernel<<<(Sn * Bn * Hn) / 64, 256>>>(k, vw, vb);

    // 2) flash attention
    const int attn_smem = (2 * 64 * 68 + 64 * 64) * sizeof(float);  // 51200 B
    cudaFuncSetAttribute(attn_kernel, cudaFuncAttributeMaxDynamicSharedMemorySize, attn_smem);
    dim3 g2(Tn / 64, Hn, Bn);
    attn_kernel<<<g2, 256, attn_smem>>>(q, k, mask);

    // 3) output projection
    dim3 g3((Tn * Bn) / 64, An / 64);
    oproj_kernel<<<g3, 256>>>(ow, ob, out);
}